// round 15
// baseline (speedup 1.0000x reference)
#include <cuda_runtime.h>
#include <math.h>
#include <stdint.h>

// Problem constants
constexpr int NB = 4;       // batch
constexpr int NT = 2048;    // seq len
constexpr int NC = 1024;    // channels
constexpr int NH = 16;      // heads
constexpr int ND = 64;      // head dim
constexpr int NM = NB * NT;     // 8192 rows
constexpr int NQKV = 3 * NC;    // 3072

// Scratch (device globals — no runtime allocation)
__device__ float g_q[NB * NH * NT * ND];   // [B,H,T,D]  (rope+0.125 scale+tf32)
__device__ float g_k[NB * NH * NT * ND];   // [B,H,T,D]  (rope+tf32)
__device__ float g_v[NB * NH * NT * ND];   // [B,H,T,D]  (tf32)
__device__ float g_y[NM * NC];             // [B*T, C]  (tf32 by attn)
__device__ float g_war[NC * NQKV];         // tf32-rounded W_attn
__device__ float g_wpr[NC * NC];           // tf32-rounded W_proj

__device__ __forceinline__ float ftf32(float x) {
    float r;
    asm("cvt.rna.tf32.f32 %0, %1;" : "=f"(r) : "f"(x));
    return r;
}

__device__ __forceinline__ void mma_tf32(float* c, const uint32_t* a, const uint32_t* b) {
    asm volatile(
        "mma.sync.aligned.m16n8k8.row.col.f32.tf32.tf32.f32 "
        "{%0,%1,%2,%3}, {%4,%5,%6,%7}, {%8,%9}, {%0,%1,%2,%3};\n"
        : "+f"(c[0]), "+f"(c[1]), "+f"(c[2]), "+f"(c[3])
        : "r"(a[0]), "r"(a[1]), "r"(a[2]), "r"(a[3]), "r"(b[0]), "r"(b[1]));
}

__device__ __forceinline__ void cp16(uint32_t dst, const void* src) {
    asm volatile("cp.async.cg.shared.global [%0], [%1], 16;\n" :: "r"(dst), "l"(src));
}
__device__ __forceinline__ void cp_commit() {
    asm volatile("cp.async.commit_group;\n" ::: "memory");
}
__device__ __forceinline__ void cp_wait1() {
    asm volatile("cp.async.wait_group 1;\n" ::: "memory");
}
__device__ __forceinline__ void cp_wait0() {
    asm volatile("cp.async.wait_group 0;\n" ::: "memory");
}

// ---------------------------------------------------------------------------
// Pre-round weights fp32 -> tf32 (x is rounded in-fragment by the QKV GEMM)
// ---------------------------------------------------------------------------
__global__ void round2_kernel(const float4* __restrict__ s0, float4* __restrict__ d0,
                              int n0,
                              const float4* __restrict__ s1, float4* __restrict__ d1,
                              int n1) {
    int total = n0 + n1;
    int stride = gridDim.x * blockDim.x;
    for (int i = blockIdx.x * blockDim.x + threadIdx.x; i < total; i += stride) {
        const float4* s; float4* d; int j = i;
        if (j < n0) { s = s0; d = d0; }
        else { j -= n0; s = s1; d = d1; }
        float4 v = s[j];
        v.x = ftf32(v.x); v.y = ftf32(v.y); v.z = ftf32(v.z); v.w = ftf32(v.w);
        d[j] = v;
    }
}

// ---------------------------------------------------------------------------
// TF32 tensor-core GEMM (R12 mainloop): 128x128 tile, BK=32, 3-stage
// cp.async, 256 threads = 8 warps of 64x32, 2 CTAs/SM.
// CVTA=true: A arrives raw fp32; ftf32 applied to A-fragments after LDS
// (bit-identical to pre-rounding: one RNA rounding per element before MMA).
// SCATTER=true (QKV): fused RoPE (+0.125 pre-scale on q) epilogue for q/k.
// ---------------------------------------------------------------------------
constexpr int GA_STG = 128 * 36;   // floats per A stage
constexpr int GB_STG = 32 * 136;   // floats per B stage
constexpr int G_BOFF = 3 * GA_STG; // B region offset (floats)
constexpr int GEMM_SMEM = (G_BOFF + 3 * GB_STG) * 4;  // 107520 B
constexpr int CST = 136;           // epilogue staging stride

template<int N, bool SCATTER, bool CVTA>
__global__ __launch_bounds__(256) void gemm_tf32(const float* __restrict__ A,
                                                 const float* __restrict__ B,
                                                 float* __restrict__ C,
                                                 const int* __restrict__ indices) {
    extern __shared__ float smg[];
    const uint32_t smem_b = (uint32_t)__cvta_generic_to_shared(smg);
    const int bx = blockIdx.x, by = blockIdx.y;
    const int tid = threadIdx.x;
    const int w = tid >> 5, lane = tid & 31;
    const int qr = lane >> 2, qc = lane & 3;
    const int wm = (w >> 2) * 64, wn = (w & 3) * 32;
    const float* Ap = A + (size_t)(by * 128) * 1024;
    const float* Bp = B + bx * 128;

    auto issue = [&](int kt, int st) {
        const int k0 = kt * 32;
        uint32_t abase = smem_b + st * GA_STG * 4;
        uint32_t bbase = smem_b + (G_BOFF + st * GB_STG) * 4;
#pragma unroll
        for (int t = 0; t < 4; t++) {
            int idx = tid + t * 256;
            int r = idx >> 3, c4 = (idx & 7) * 4;
            cp16(abase + (r * 36 + c4) * 4, Ap + (size_t)r * 1024 + k0 + c4);
            int rb = idx >> 5, cb = (idx & 31) * 4;
            cp16(bbase + (rb * 136 + cb) * 4, Bp + (size_t)(k0 + rb) * N + cb);
        }
        cp_commit();
    };

    float acc[4][4][4];
#pragma unroll
    for (int i = 0; i < 4; i++)
#pragma unroll
        for (int j = 0; j < 4; j++)
#pragma unroll
            for (int u = 0; u < 4; u++) acc[i][j][u] = 0.0f;

    issue(0, 0); issue(1, 1);

    for (int kt = 0; kt < 32; kt++) {
        const int st = kt % 3;
        if (kt < 31) cp_wait1(); else cp_wait0();
        __syncthreads();
        if (kt + 2 < 32) issue(kt + 2, (kt + 2) % 3);
        const float* As = smg + st * GA_STG;
        const float* Bs = smg + G_BOFF + st * GB_STG;
#pragma unroll
        for (int kc = 0; kc < 32; kc += 8) {
            uint32_t af[4][4], bf[4][2];
#pragma unroll
            for (int i = 0; i < 4; i++) {
                const float* ar = As + (wm + i * 16 + qr) * 36 + kc + qc;
                if (CVTA) {
                    af[i][0] = __float_as_uint(ftf32(ar[0]));
                    af[i][1] = __float_as_uint(ftf32(ar[8 * 36]));
                    af[i][2] = __float_as_uint(ftf32(ar[4]));
                    af[i][3] = __float_as_uint(ftf32(ar[8 * 36 + 4]));
                } else {
                    af[i][0] = __float_as_uint(ar[0]);
                    af[i][1] = __float_as_uint(ar[8 * 36]);
                    af[i][2] = __float_as_uint(ar[4]);
                    af[i][3] = __float_as_uint(ar[8 * 36 + 4]);
                }
            }
#pragma unroll
            for (int j = 0; j < 4; j++) {
                bf[j][0] = __float_as_uint(Bs[(kc + qc) * 136 + wn + j * 8 + qr]);
                bf[j][1] = __float_as_uint(Bs[(kc + 4 + qc) * 136 + wn + j * 8 + qr]);
            }
#pragma unroll
            for (int i = 0; i < 4; i++)
#pragma unroll
                for (int j = 0; j < 4; j++) mma_tf32(acc[i][j], af[i], bf[j]);
        }
    }

    if (!SCATTER) {
#pragma unroll
        for (int i = 0; i < 4; i++)
#pragma unroll
            for (int j = 0; j < 4; j++) {
                int r0 = by * 128 + wm + i * 16 + qr;
                int c0 = bx * 128 + wn + j * 8 + 2 * qc;
#pragma unroll
                for (int u = 0; u < 4; u++)
                    C[(size_t)(r0 + (u >> 1) * 8) * NC + c0 + (u & 1)] = acc[i][j][u];
            }
        return;
    }

    const int part = bx >> 3;   // 0=q, 1=k, 2=v
    if (part == 2) {
#pragma unroll
        for (int i = 0; i < 4; i++)
#pragma unroll
            for (int j = 0; j < 4; j++) {
                int r0 = by * 128 + wm + i * 16 + qr;
                int c0 = bx * 128 + wn + j * 8 + 2 * qc;
#pragma unroll
                for (int u = 0; u < 4; u++) {
                    int row = r0 + (u >> 1) * 8;
                    int col = c0 + (u & 1);
                    int b = row >> 11, t = row & 2047;
                    int c = col & 1023;
                    int h = c >> 6, d = c & 63;
                    g_v[(size_t)(((b * NH + h) * NT) + t) * ND + d] = ftf32(acc[i][j][u]);
                }
            }
        return;
    }

    // q/k: stage -> rope (+0.125 pre-scale for q) -> coalesced scatter
    float* Cs = smg;
    __syncthreads();
#pragma unroll
    for (int i = 0; i < 4; i++)
#pragma unroll
        for (int j = 0; j < 4; j++) {
            int rl0 = wm + i * 16 + qr;
            int cl0 = wn + j * 8 + 2 * qc;
#pragma unroll
            for (int u = 0; u < 4; u++)
                Cs[(rl0 + (u >> 1) * 8) * CST + cl0 + (u & 1)] = acc[i][j][u];
        }
    __syncthreads();

    // 0.125 is a power of two: scaling before ftf32 commutes exactly with
    // rounding and with fp32 MMA accumulation -> bit-identical to scaling S.
    const float qsc = (part == 0) ? 0.125f : 1.0f;
    const float invf = expf(-9.210340371976184f * (float)lane * (1.0f / 32.0f));
#pragma unroll
    for (int it = 0; it < 16; it++) {
        int r = it * 8 + w;
        int grow = by * 128 + r;
        int pos = indices[(grow >> 11) * NT + (grow & 2047)];
        float ang = (float)pos * invf;
        float sv, cv;
        sincosf(ang, &sv, &cv);
#pragma unroll
        for (int hh = 0; hh < 2; hh++) {
            int base = r * CST + hh * 64 + lane;
            float x1 = Cs[base], x2 = Cs[base + 32];
            Cs[base]      = ftf32((x1 * cv - x2 * sv) * qsc);
            Cs[base + 32] = ftf32((x1 * sv + x2 * cv) * qsc);
        }
    }
    __syncthreads();

    float* dst = (part == 0) ? g_q : g_k;
#pragma unroll
    for (int t2 = 0; t2 < 16; t2++) {
        int idx = tid + t2 * 256;
        int r = idx >> 5, c4 = (idx & 31) * 4;
        float4 v = *(float4*)&Cs[r * CST + c4];
        int grow = by * 128 + r;
        int b = grow >> 11, t = grow & 2047;
        int col = bx * 128 + c4;
        int c = col & 1023;
        int h = c >> 6, d = c & 63;
        *(float4*)&dst[(size_t)(((b * NH + h) * NT) + t) * ND + d] = v;
    }
}

// ---------------------------------------------------------------------------
// Flash attention (R12 config + Q pre-scaled; warp-uniform mask skip).
// ---------------------------------------------------------------------------
constexpr int QSTR = 68;
constexpr int KSTR = 68;
constexpr int VSTR = 72;
constexpr int OFF_K = 128 * QSTR;                 // 8704
constexpr int OFF_V = OFF_K + 2 * 64 * KSTR;      // 17408
constexpr int OFF_I = OFF_V + 2 * 64 * VSTR;      // 26624
constexpr int SMEM_WORDS = OFF_I + 2 * 64;        // 26752 words = 107008 B

__global__ __launch_bounds__(128) void attn_kernel(const int* __restrict__ indices) {
    const int qt = (gridDim.x - 1) - blockIdx.x;   // heavy blocks first
    const int h = blockIdx.y;
    const int b = blockIdx.z;
    const int q0 = qt * 128;
    const int tid = threadIdx.x;
    const int w = tid >> 5, lane = tid & 31;
    const int qr = lane >> 2, qc = lane & 3;
    const int rw = w * 32;

    extern __shared__ float sm[];
    float* Qs = sm;
    const uint32_t smem_b = (uint32_t)__cvta_generic_to_shared(sm);

    const size_t head_base = (size_t)((b * NH + h) * NT) * ND;
    const float* kg_base = g_k + head_base;
    const float* vg_base = g_v + head_base;
    const int* idx_base = indices + b * NT;

    auto issue_tile = [&](int kt, int buf) {
        const float* kg = kg_base + (size_t)(kt * 64) * ND;
        const float* vg = vg_base + (size_t)(kt * 64) * ND;
        uint32_t kdst = smem_b + (OFF_K + buf * 64 * KSTR) * 4;
        uint32_t vdst = smem_b + (OFF_V + buf * 64 * VSTR) * 4;
#pragma unroll
        for (int t = 0; t < 8; t++) {
            int idx = tid + t * 128;
            int r = idx >> 4, c4 = (idx & 15) * 4;
            cp16(kdst + (r * KSTR + c4) * 4, kg + r * ND + c4);
            cp16(vdst + (r * VSTR + c4) * 4, vg + r * ND + c4);
        }
        if (tid < 16)
            cp16(smem_b + (OFF_I + buf * 64 + tid * 4) * 4, idx_base + kt * 64 + tid * 4);
    };

#pragma unroll
    for (int t = 0; t < 16; t++) {
        int idx = tid + t * 128;
        int r = idx >> 4, d4 = (idx & 15) * 4;
        *(float4*)&Qs[r * QSTR + d4] =
            *(const float4*)(g_q + head_base + (size_t)(q0 + r) * ND + d4);
    }
    int qi[4];
#pragma unroll
    for (int mi = 0; mi < 2; mi++) {
        qi[mi * 2 + 0] = idx_base[q0 + rw + mi * 16 + qr];
        qi[mi * 2 + 1] = idx_base[q0 + rw + mi * 16 + qr + 8];
    }
    int qmin = min(min(qi[0], qi[1]), min(qi[2], qi[3]));
#pragma unroll
    for (int off = 16; off >= 4; off >>= 1)
        qmin = min(qmin, __shfl_xor_sync(0xffffffffu, qmin, off));

    float mrow[4], lrow[4];
#pragma unroll
    for (int u = 0; u < 4; u++) { mrow[u] = -INFINITY; lrow[u] = 0.0f; }
    float o[2][8][4];
#pragma unroll
    for (int mi = 0; mi < 2; mi++)
#pragma unroll
        for (int j = 0; j < 8; j++)
#pragma unroll
            for (int u = 0; u < 4; u++) o[mi][j][u] = 0.0f;

    const int ktmax = 2 * qt + 1;
    issue_tile(0, 0); cp_commit();
    issue_tile(1, 1); cp_commit();

    for (int kt = 0; kt <= ktmax; kt++) {
        const int buf = kt & 1;
        float* Ks = sm + OFF_K + buf * 64 * KSTR;
        float* Vs = sm + OFF_V + buf * 64 * VSTR;
        const int* kidx = (const int*)(sm + OFF_I + buf * 64);

        if (kt < ktmax) cp_wait1(); else cp_wait0();
        __syncthreads();

        int kmax = max(kidx[lane], kidx[lane + 32]);
#pragma unroll
        for (int off = 16; off >= 1; off >>= 1)
            kmax = max(kmax, __shfl_xor_sync(0xffffffffu, kmax, off));
        const bool needmask = (kmax > qmin);   // warp-uniform

        float s[2][8][4];
#pragma unroll
        for (int mi = 0; mi < 2; mi++)
#pragma unroll
            for (int j = 0; j < 8; j++)
#pragma unroll
                for (int u = 0; u < 4; u++) s[mi][j][u] = 0.0f;
#pragma unroll
        for (int kc = 0; kc < 8; kc++) {
            uint32_t af[2][4];
#pragma unroll
            for (int mi = 0; mi < 2; mi++) {
                int r0 = (rw + mi * 16 + qr) * QSTR + kc * 8 + qc;
                af[mi][0] = __float_as_uint(Qs[r0]);
                af[mi][1] = __float_as_uint(Qs[r0 + 8 * QSTR]);
                af[mi][2] = __float_as_uint(Qs[r0 + 4]);
                af[mi][3] = __float_as_uint(Qs[r0 + 8 * QSTR + 4]);
            }
#pragma unroll
            for (int j = 0; j < 8; j++) {
                uint32_t bf[2];
                bf[0] = __float_as_uint(Ks[(j * 8 + qr) * KSTR + kc * 8 + qc]);
                bf[1] = __float_as_uint(Ks[(j * 8 + qr) * KSTR + kc * 8 + qc + 4]);
                mma_tf32(s[0][j], af[0], bf);
                mma_tf32(s[1][j], af[1], bf);
            }
        }

        if (needmask) {
#pragma unroll
            for (int mi = 0; mi < 2; mi++)
#pragma unroll
                for (int j = 0; j < 8; j++) {
                    int c0 = j * 8 + 2 * qc;
                    int kd0 = kidx[c0], kd1 = kidx[c0 + 1];
                    if (kd0 > qi[mi * 2 + 0]) s[mi][j][0] = -INFINITY;
                    if (kd1 > qi[mi * 2 + 0]) s[mi][j][1] = -INFINITY;
                    if (kd0 > qi[mi * 2 + 1]) s[mi][j][2] = -INFINITY;
                    if (kd1 > qi[mi * 2 + 1]) s[mi][j][3] = -INFINITY;
                }
        }

#pragma unroll
        for (int mi = 0; mi < 2; mi++) {
            float tm0 = -INFINITY, tm1 = -INFINITY;
#pragma unroll
            for (int j = 0; j < 8; j++) {
                tm0 = fmaxf(tm0, fmaxf(s[mi][j][0], s[mi][j][1]));
                tm1 = fmaxf(tm1, fmaxf(s[mi][j][2], s[mi][j][3]));
            }
#pragma unroll
            for (int off = 1; off < 4; off <<= 1) {
                tm0 = fmaxf(tm0, __shfl_xor_sync(0xffffffffu, tm0, off));
                tm1 = fmaxf(tm1, __shfl_xor_sync(0xffffffffu, tm1, off));
            }
            float nm0 = fmaxf(mrow[mi * 2 + 0], tm0);
            float nm1 = fmaxf(mrow[mi * 2 + 1], tm1);
            float a0 = __expf(mrow[mi * 2 + 0] - nm0);
            float a1 = __expf(mrow[mi * 2 + 1] - nm1);
            mrow[mi * 2 + 0] = nm0; mrow[mi * 2 + 1] = nm1;
            float rs0 = 0.0f, rs1 = 0.0f;
#pragma unroll
            for (int j = 0; j < 8; j++) {
                s[mi][j][0] = ftf32(__expf(s[mi][j][0] - nm0));
                s[mi][j][1] = ftf32(__expf(s[mi][j][1] - nm0));
                s[mi][j][2] = ftf32(__expf(s[mi][j][2] - nm1));
                s[mi][j][3] = ftf32(__expf(s[mi][j][3] - nm1));
                rs0 += s[mi][j][0] + s[mi][j][1];
                rs1 += s[mi][j][2] + s[mi][j][3];
            }
#pragma unroll
            for (int off = 1; off < 4; off <<= 1) {
                rs0 += __shfl_xor_sync(0xffffffffu, rs0, off);
                rs1 += __shfl_xor_sync(0xffffffffu, rs1, off);
            }
            lrow[mi * 2 + 0] = lrow[mi * 2 + 0] * a0 + rs0;
            lrow[mi * 2 + 1] = lrow[mi * 2 + 1] * a1 + rs1;
#pragma unroll
            for (int j = 0; j < 8; j++) {
                o[mi][j][0] *= a0; o[mi][j][1] *= a0;
                o[mi][j][2] *= a1; o[mi][j][3] *= a1;
            }
        }

        const int src0 = (lane & ~3) | (qc >> 1);
        const int src1 = src0 + 2;
        const bool odd = (qc & 1);
#pragma unroll
        for (int kc = 0; kc < 8; kc++) {
            uint32_t af[2][4];
#pragma unroll
            for (int mi = 0; mi < 2; mi++) {
                float p0 = s[mi][kc][0], p1 = s[mi][kc][1];
                float p2 = s[mi][kc][2], p3 = s[mi][kc][3];
                float t00 = __shfl_sync(0xffffffffu, p0, src0);
                float t01 = __shfl_sync(0xffffffffu, p1, src0);
                float t10 = __shfl_sync(0xffffffffu, p0, src1);
                float t11 = __shfl_sync(0xffffffffu, p1, src1);
                float u00 = __shfl_sync(0xffffffffu, p2, src0);
                float u01 = __shfl_sync(0xffffffffu, p3, src0);
                float u10 = __shfl_sync(0xffffffffu, p2, src1);
                float u11 = __shfl_sync(0xffffffffu, p3, src1);
                af[mi][0] = __float_as_uint(odd ? t01 : t00);
                af[mi][1] = __float_as_uint(odd ? u01 : u00);
                af[mi][2] = __float_as_uint(odd ? t11 : t10);
                af[mi][3] = __float_as_uint(odd ? u11 : u10);
            }
#pragma unroll
            for (int j = 0; j < 8; j++) {
                uint32_t bf[2];
                bf[0] = __float_as_uint(Vs[(kc * 8 + qc) * VSTR + j * 8 + qr]);
                bf[1] = __float_as_uint(Vs[(kc * 8 + qc + 4) * VSTR + j * 8 + qr]);
                mma_tf32(o[0][j], af[0], bf);
                mma_tf32(o[1][j], af[1], bf);
            }
        }

        __syncthreads();
        if (kt + 2 <= ktmax) { issue_tile(kt + 2, buf); cp_commit(); }
    }

    // finalize: divide by l, tf32-round (proj GEMM consumes directly)
#pragma unroll
    for (int mi = 0; mi < 2; mi++) {
        float inv0 = 1.0f / lrow[mi * 2 + 0];
        float inv1 = 1.0f / lrow[mi * 2 + 1];
        size_t out0 = (size_t)(b * NT + q0 + rw + mi * 16 + qr) * NC + h * 64;
        size_t out1 = (size_t)(b * NT + q0 + rw + mi * 16 + qr + 8) * NC + h * 64;
#pragma unroll
        for (int j = 0; j < 8; j++) {
            int c0 = j * 8 + 2 * qc;
            float2 v0; v0.x = ftf32(o[mi][j][0] * inv0); v0.y = ftf32(o[mi][j][1] * inv0);
            float2 v1; v1.x = ftf32(o[mi][j][2] * inv1); v1.y = ftf32(o[mi][j][3] * inv1);
            *(float2*)&g_y[out0 + c0] = v0;
            *(float2*)&g_y[out1 + c0] = v1;
        }
    }
}

// ---------------------------------------------------------------------------
extern "C" void kernel_launch(void* const* d_in, const int* in_sizes, int n_in,
                              void* d_out, int out_size) {
    const float* x       = (const float*)d_in[0];
    const float* W_attn  = (const float*)d_in[1];
    const float* W_proj  = (const float*)d_in[2];
    const int*   indices = (const int*)d_in[3];
    float* out = (float*)d_out;

    static float *p_y = nullptr, *p_war = nullptr, *p_wpr = nullptr;
    const int attn_smem = SMEM_WORDS * 4;   // 107008 B
    if (p_y == nullptr) {
        cudaFuncSetAttribute(attn_kernel, cudaFuncAttributeMaxDynamicSharedMemorySize,
                             attn_smem);
        cudaFuncSetAttribute(gemm_tf32<NQKV, true, true>,
                             cudaFuncAttributeMaxDynamicSharedMemorySize, GEMM_SMEM);
        cudaFuncSetAttribute(gemm_tf32<NC, false, false>,
                             cudaFuncAttributeMaxDynamicSharedMemorySize, GEMM_SMEM);
        void* p;
        cudaGetSymbolAddress(&p, g_y);   p_y   = (float*)p;
        cudaGetSymbolAddress(&p, g_war); p_war = (float*)p;
        cudaGetSymbolAddress(&p, g_wpr); p_wpr = (float*)p;
    }

    // pre-round weights only (x is rounded in-fragment inside the QKV GEMM)
    round2_kernel<<<592, 256>>>(
        (const float4*)W_attn, (float4*)p_war, NC * NQKV / 4,
        (const float4*)W_proj, (float4*)p_wpr, NC * NC / 4);

    // QKV GEMM: raw x as A (CVTA), pre-rounded W_attn as B; fused RoPE epilogue
    gemm_tf32<NQKV, true, true><<<dim3(NQKV / 128, NM / 128), 256, GEMM_SMEM>>>(
        x, p_war, nullptr, indices);

    attn_kernel<<<dim3(NT / 128, NH, NB), 128, attn_smem>>>(indices);

    gemm_tf32<NC, false, false><<<dim3(NC / 128, NM / 128), 256, GEMM_SMEM>>>(
        p_y, p_wpr, out, nullptr);
}

// round 16
// speedup vs baseline: 1.0307x; 1.0307x over previous
#include <cuda_runtime.h>
#include <math.h>
#include <stdint.h>

// Problem constants
constexpr int NB = 4;       // batch
constexpr int NT = 2048;    // seq len
constexpr int NC = 1024;    // channels
constexpr int NH = 16;      // heads
constexpr int ND = 64;      // head dim
constexpr int NM = NB * NT;     // 8192 rows
constexpr int NQKV = 3 * NC;    // 3072

// Scratch (device globals — no runtime allocation)
__device__ float g_q[NB * NH * NT * ND];   // [B,H,T,D]  (rope+tf32 by gemm epilogue)
__device__ float g_k[NB * NH * NT * ND];   // [B,H,T,D]  (rope+tf32 by gemm epilogue)
__device__ float g_v[NB * NH * NT * ND];   // [B,H,T,D]  (tf32)
__device__ float g_y[NM * NC];             // [B*T, C]  (tf32 by attn)
__device__ float g_xr[NM * NC];            // tf32-rounded x
__device__ float g_war[NC * NQKV];         // tf32-rounded W_attn
__device__ float g_wpr[NC * NC];           // tf32-rounded W_proj

__device__ __forceinline__ float ftf32(float x) {
    float r;
    asm("cvt.rna.tf32.f32 %0, %1;" : "=f"(r) : "f"(x));
    return r;
}

__device__ __forceinline__ void mma_tf32(float* c, const uint32_t* a, const uint32_t* b) {
    asm volatile(
        "mma.sync.aligned.m16n8k8.row.col.f32.tf32.tf32.f32 "
        "{%0,%1,%2,%3}, {%4,%5,%6,%7}, {%8,%9}, {%0,%1,%2,%3};\n"
        : "+f"(c[0]), "+f"(c[1]), "+f"(c[2]), "+f"(c[3])
        : "r"(a[0]), "r"(a[1]), "r"(a[2]), "r"(a[3]), "r"(b[0]), "r"(b[1]));
}

__device__ __forceinline__ void cp16(uint32_t dst, const void* src) {
    asm volatile("cp.async.cg.shared.global [%0], [%1], 16;\n" :: "r"(dst), "l"(src));
}
__device__ __forceinline__ void cp_commit() {
    asm volatile("cp.async.commit_group;\n" ::: "memory");
}
__device__ __forceinline__ void cp_wait1() {
    asm volatile("cp.async.wait_group 1;\n" ::: "memory");
}
__device__ __forceinline__ void cp_wait0() {
    asm volatile("cp.async.wait_group 0;\n" ::: "memory");
}

// ---------------------------------------------------------------------------
// Merged pre-round fp32 -> tf32 for x, W_attn, W_proj (one launch)
// ---------------------------------------------------------------------------
__global__ void round3_kernel(const float4* __restrict__ s0, float4* __restrict__ d0,
                              int n0,
                              const float4* __restrict__ s1, float4* __restrict__ d1,
                              int n1,
                              const float4* __restrict__ s2, float4* __restrict__ d2,
                              int n2) {
    int total = n0 + n1 + n2;
    int stride = gridDim.x * blockDim.x;
    for (int i = blockIdx.x * blockDim.x + threadIdx.x; i < total; i += stride) {
        const float4* s; float4* d; int j = i;
        if (j < n0) { s = s0; d = d0; }
        else if ((j -= n0) < n1) { s = s1; d = d1; }
        else { j -= n1; s = s2; d = d2; }
        float4 v = s[j];
        v.x = ftf32(v.x); v.y = ftf32(v.y); v.z = ftf32(v.z); v.w = ftf32(v.w);
        d[j] = v;
    }
}

// ---------------------------------------------------------------------------
// TF32 tensor-core GEMM (R12 exact): 128x128 tile, BK=32, 3-stage cp.async,
// 256 threads = 8 warps of 64x32, 2 CTAs/SM.
// SCATTER=true (QKV): fused RoPE epilogue for q/k; v direct scatter.
// ---------------------------------------------------------------------------
constexpr int GA_STG = 128 * 36;   // floats per A stage
constexpr int GB_STG = 32 * 136;   // floats per B stage
constexpr int G_BOFF = 3 * GA_STG; // B region offset (floats)
constexpr int GEMM_SMEM = (G_BOFF + 3 * GB_STG) * 4;  // 107520 B
constexpr int CST = 136;           // epilogue staging stride

template<int N, bool SCATTER>
__global__ __launch_bounds__(256) void gemm_tf32(const float* __restrict__ A,
                                                 const float* __restrict__ B,
                                                 float* __restrict__ C,
                                                 const int* __restrict__ indices) {
    extern __shared__ float smg[];
    const uint32_t smem_b = (uint32_t)__cvta_generic_to_shared(smg);
    const int bx = blockIdx.x, by = blockIdx.y;
    const int tid = threadIdx.x;
    const int w = tid >> 5, lane = tid & 31;
    const int qr = lane >> 2, qc = lane & 3;
    const int wm = (w >> 2) * 64, wn = (w & 3) * 32;
    const float* Ap = A + (size_t)(by * 128) * 1024;
    const float* Bp = B + bx * 128;

    auto issue = [&](int kt, int st) {
        const int k0 = kt * 32;
        uint32_t abase = smem_b + st * GA_STG * 4;
        uint32_t bbase = smem_b + (G_BOFF + st * GB_STG) * 4;
#pragma unroll
        for (int t = 0; t < 4; t++) {
            int idx = tid + t * 256;
            int r = idx >> 3, c4 = (idx & 7) * 4;
            cp16(abase + (r * 36 + c4) * 4, Ap + (size_t)r * 1024 + k0 + c4);
            int rb = idx >> 5, cb = (idx & 31) * 4;
            cp16(bbase + (rb * 136 + cb) * 4, Bp + (size_t)(k0 + rb) * N + cb);
        }
        cp_commit();
    };

    float acc[4][4][4];
#pragma unroll
    for (int i = 0; i < 4; i++)
#pragma unroll
        for (int j = 0; j < 4; j++)
#pragma unroll
            for (int u = 0; u < 4; u++) acc[i][j][u] = 0.0f;

    issue(0, 0); issue(1, 1);

    for (int kt = 0; kt < 32; kt++) {
        const int st = kt % 3;
        if (kt < 31) cp_wait1(); else cp_wait0();
        __syncthreads();
        if (kt + 2 < 32) issue(kt + 2, (kt + 2) % 3);
        const float* As = smg + st * GA_STG;
        const float* Bs = smg + G_BOFF + st * GB_STG;
#pragma unroll
        for (int kc = 0; kc < 32; kc += 8) {
            uint32_t af[4][4], bf[4][2];
#pragma unroll
            for (int i = 0; i < 4; i++) {
                const float* ar = As + (wm + i * 16 + qr) * 36 + kc + qc;
                af[i][0] = __float_as_uint(ar[0]);
                af[i][1] = __float_as_uint(ar[8 * 36]);
                af[i][2] = __float_as_uint(ar[4]);
                af[i][3] = __float_as_uint(ar[8 * 36 + 4]);
            }
#pragma unroll
            for (int j = 0; j < 4; j++) {
                bf[j][0] = __float_as_uint(Bs[(kc + qc) * 136 + wn + j * 8 + qr]);
                bf[j][1] = __float_as_uint(Bs[(kc + 4 + qc) * 136 + wn + j * 8 + qr]);
            }
#pragma unroll
            for (int i = 0; i < 4; i++)
#pragma unroll
                for (int j = 0; j < 4; j++) mma_tf32(acc[i][j], af[i], bf[j]);
        }
    }

    if (!SCATTER) {
#pragma unroll
        for (int i = 0; i < 4; i++)
#pragma unroll
            for (int j = 0; j < 4; j++) {
                int r0 = by * 128 + wm + i * 16 + qr;
                int c0 = bx * 128 + wn + j * 8 + 2 * qc;
#pragma unroll
                for (int u = 0; u < 4; u++)
                    C[(size_t)(r0 + (u >> 1) * 8) * NC + c0 + (u & 1)] = acc[i][j][u];
            }
        return;
    }

    const int part = bx >> 3;   // 0=q, 1=k, 2=v
    if (part == 2) {
#pragma unroll
        for (int i = 0; i < 4; i++)
#pragma unroll
            for (int j = 0; j < 4; j++) {
                int r0 = by * 128 + wm + i * 16 + qr;
                int c0 = bx * 128 + wn + j * 8 + 2 * qc;
#pragma unroll
                for (int u = 0; u < 4; u++) {
                    int row = r0 + (u >> 1) * 8;
                    int col = c0 + (u & 1);
                    int b = row >> 11, t = row & 2047;
                    int c = col & 1023;
                    int h = c >> 6, d = c & 63;
                    g_v[(size_t)(((b * NH + h) * NT) + t) * ND + d] = ftf32(acc[i][j][u]);
                }
            }
        return;
    }

    // q/k: stage -> rope in place -> coalesced scatter
    float* Cs = smg;
    __syncthreads();
#pragma unroll
    for (int i = 0; i < 4; i++)
#pragma unroll
        for (int j = 0; j < 4; j++) {
            int rl0 = wm + i * 16 + qr;
            int cl0 = wn + j * 8 + 2 * qc;
#pragma unroll
            for (int u = 0; u < 4; u++)
                Cs[(rl0 + (u >> 1) * 8) * CST + cl0 + (u & 1)] = acc[i][j][u];
        }
    __syncthreads();

    const float invf = expf(-9.210340371976184f * (float)lane * (1.0f / 32.0f));
#pragma unroll
    for (int it = 0; it < 16; it++) {
        int r = it * 8 + w;
        int grow = by * 128 + r;
        int pos = indices[(grow >> 11) * NT + (grow & 2047)];
        float ang = (float)pos * invf;
        float sv, cv;
        sincosf(ang, &sv, &cv);
#pragma unroll
        for (int hh = 0; hh < 2; hh++) {
            int base = r * CST + hh * 64 + lane;
            float x1 = Cs[base], x2 = Cs[base + 32];
            Cs[base]      = ftf32(x1 * cv - x2 * sv);
            Cs[base + 32] = ftf32(x1 * sv + x2 * cv);
        }
    }
    __syncthreads();

    float* dst = (part == 0) ? g_q : g_k;
#pragma unroll
    for (int t2 = 0; t2 < 16; t2++) {
        int idx = tid + t2 * 256;
        int r = idx >> 5, c4 = (idx & 31) * 4;
        float4 v = *(float4*)&Cs[r * CST + c4];
        int grow = by * 128 + r;
        int b = grow >> 11, t = grow & 2047;
        int col = bx * 128 + c4;
        int c = col & 1023;
        int h = c >> 6, d = c & 63;
        *(float4*)&dst[(size_t)(((b * NH + h) * NT) + t) * ND + d] = v;
    }
}

// ---------------------------------------------------------------------------
// Flash attention (R12 config; warp-uniform interior-tile mask skip).
// NEW vs R12: Q tile loaded via cp.async as its OWN group issued FIRST, so
// the existing cp_wait1 at kt=0 (2 groups outstanding allowed -> Q + tile0
// complete) covers it and Q-load latency overlaps tile0/tile1 issue.
// ---------------------------------------------------------------------------
constexpr int QSTR = 68;
constexpr int KSTR = 68;
constexpr int VSTR = 72;
constexpr int OFF_K = 128 * QSTR;                 // 8704
constexpr int OFF_V = OFF_K + 2 * 64 * KSTR;      // 17408
constexpr int OFF_I = OFF_V + 2 * 64 * VSTR;      // 26624
constexpr int SMEM_WORDS = OFF_I + 2 * 64;        // 26752 words = 107008 B

__global__ __launch_bounds__(128) void attn_kernel(const int* __restrict__ indices) {
    const int qt = (gridDim.x - 1) - blockIdx.x;   // heavy blocks first
    const int h = blockIdx.y;
    const int b = blockIdx.z;
    const int q0 = qt * 128;
    const int tid = threadIdx.x;
    const int w = tid >> 5, lane = tid & 31;
    const int qr = lane >> 2, qc = lane & 3;
    const int rw = w * 32;

    extern __shared__ float sm[];
    float* Qs = sm;
    const uint32_t smem_b = (uint32_t)__cvta_generic_to_shared(sm);

    const size_t head_base = (size_t)((b * NH + h) * NT) * ND;
    const float* kg_base = g_k + head_base;
    const float* vg_base = g_v + head_base;
    const int* idx_base = indices + b * NT;

    auto issue_tile = [&](int kt, int buf) {
        const float* kg = kg_base + (size_t)(kt * 64) * ND;
        const float* vg = vg_base + (size_t)(kt * 64) * ND;
        uint32_t kdst = smem_b + (OFF_K + buf * 64 * KSTR) * 4;
        uint32_t vdst = smem_b + (OFF_V + buf * 64 * VSTR) * 4;
#pragma unroll
        for (int t = 0; t < 8; t++) {
            int idx = tid + t * 128;
            int r = idx >> 4, c4 = (idx & 15) * 4;
            cp16(kdst + (r * KSTR + c4) * 4, kg + r * ND + c4);
            cp16(vdst + (r * VSTR + c4) * 4, vg + r * ND + c4);
        }
        if (tid < 16)
            cp16(smem_b + (OFF_I + buf * 64 + tid * 4) * 4, idx_base + kt * 64 + tid * 4);
    };

    // Q tile via cp.async (group 0 — issued before tile0/tile1)
    {
        const float* qg = g_q + head_base + (size_t)q0 * ND;
#pragma unroll
        for (int t = 0; t < 16; t++) {
            int idx = tid + t * 128;
            int r = idx >> 4, d4 = (idx & 15) * 4;
            cp16(smem_b + (r * QSTR + d4) * 4, qg + r * ND + d4);
        }
        cp_commit();
    }

    int qi[4];
#pragma unroll
    for (int mi = 0; mi < 2; mi++) {
        qi[mi * 2 + 0] = idx_base[q0 + rw + mi * 16 + qr];
        qi[mi * 2 + 1] = idx_base[q0 + rw + mi * 16 + qr + 8];
    }
    int qmin = min(min(qi[0], qi[1]), min(qi[2], qi[3]));
#pragma unroll
    for (int off = 16; off >= 4; off >>= 1)
        qmin = min(qmin, __shfl_xor_sync(0xffffffffu, qmin, off));

    float mrow[4], lrow[4];
#pragma unroll
    for (int u = 0; u < 4; u++) { mrow[u] = -INFINITY; lrow[u] = 0.0f; }
    float o[2][8][4];
#pragma unroll
    for (int mi = 0; mi < 2; mi++)
#pragma unroll
        for (int j = 0; j < 8; j++)
#pragma unroll
            for (int u = 0; u < 4; u++) o[mi][j][u] = 0.0f;

    const int ktmax = 2 * qt + 1;
    issue_tile(0, 0); cp_commit();   // group 1
    issue_tile(1, 1); cp_commit();   // group 2

    for (int kt = 0; kt <= ktmax; kt++) {
        const int buf = kt & 1;
        float* Ks = sm + OFF_K + buf * 64 * KSTR;
        float* Vs = sm + OFF_V + buf * 64 * VSTR;
        const int* kidx = (const int*)(sm + OFF_I + buf * 64);

        // kt=0: wait_group 1 leaves only the newest group (tile1) outstanding
        // -> Q (g0) and tile0 (g1) are complete. Later iterations identical
        // to R12 (1 outstanding = next tile).
        if (kt < ktmax) cp_wait1(); else cp_wait0();
        __syncthreads();

        int kmax = max(kidx[lane], kidx[lane + 32]);
#pragma unroll
        for (int off = 16; off >= 1; off >>= 1)
            kmax = max(kmax, __shfl_xor_sync(0xffffffffu, kmax, off));
        const bool needmask = (kmax > qmin);   // warp-uniform

        float s[2][8][4];
#pragma unroll
        for (int mi = 0; mi < 2; mi++)
#pragma unroll
            for (int j = 0; j < 8; j++)
#pragma unroll
                for (int u = 0; u < 4; u++) s[mi][j][u] = 0.0f;
#pragma unroll
        for (int kc = 0; kc < 8; kc++) {
            uint32_t af[2][4];
#pragma unroll
            for (int mi = 0; mi < 2; mi++) {
                int r0 = (rw + mi * 16 + qr) * QSTR + kc * 8 + qc;
                af[mi][0] = __float_as_uint(Qs[r0]);
                af[mi][1] = __float_as_uint(Qs[r0 + 8 * QSTR]);
                af[mi][2] = __float_as_uint(Qs[r0 + 4]);
                af[mi][3] = __float_as_uint(Qs[r0 + 8 * QSTR + 4]);
            }
#pragma unroll
            for (int j = 0; j < 8; j++) {
                uint32_t bf[2];
                bf[0] = __float_as_uint(Ks[(j * 8 + qr) * KSTR + kc * 8 + qc]);
                bf[1] = __float_as_uint(Ks[(j * 8 + qr) * KSTR + kc * 8 + qc + 4]);
                mma_tf32(s[0][j], af[0], bf);
                mma_tf32(s[1][j], af[1], bf);
            }
        }

        // scale (+ mask only when it can fire)
        if (needmask) {
#pragma unroll
            for (int mi = 0; mi < 2; mi++)
#pragma unroll
                for (int j = 0; j < 8; j++) {
                    int c0 = j * 8 + 2 * qc;
                    int kd0 = kidx[c0], kd1 = kidx[c0 + 1];
                    s[mi][j][0] = (kd0 > qi[mi * 2 + 0]) ? -INFINITY : s[mi][j][0] * 0.125f;
                    s[mi][j][1] = (kd1 > qi[mi * 2 + 0]) ? -INFINITY : s[mi][j][1] * 0.125f;
                    s[mi][j][2] = (kd0 > qi[mi * 2 + 1]) ? -INFINITY : s[mi][j][2] * 0.125f;
                    s[mi][j][3] = (kd1 > qi[mi * 2 + 1]) ? -INFINITY : s[mi][j][3] * 0.125f;
                }
        } else {
#pragma unroll
            for (int mi = 0; mi < 2; mi++)
#pragma unroll
                for (int j = 0; j < 8; j++)
#pragma unroll
                    for (int u = 0; u < 4; u++) s[mi][j][u] *= 0.125f;
        }

#pragma unroll
        for (int mi = 0; mi < 2; mi++) {
            float tm0 = -INFINITY, tm1 = -INFINITY;
#pragma unroll
            for (int j = 0; j < 8; j++) {
                tm0 = fmaxf(tm0, fmaxf(s[mi][j][0], s[mi][j][1]));
                tm1 = fmaxf(tm1, fmaxf(s[mi][j][2], s[mi][j][3]));
            }
#pragma unroll
            for (int off = 1; off < 4; off <<= 1) {
                tm0 = fmaxf(tm0, __shfl_xor_sync(0xffffffffu, tm0, off));
                tm1 = fmaxf(tm1, __shfl_xor_sync(0xffffffffu, tm1, off));
            }
            float nm0 = fmaxf(mrow[mi * 2 + 0], tm0);
            float nm1 = fmaxf(mrow[mi * 2 + 1], tm1);
            float a0 = __expf(mrow[mi * 2 + 0] - nm0);
            float a1 = __expf(mrow[mi * 2 + 1] - nm1);
            mrow[mi * 2 + 0] = nm0; mrow[mi * 2 + 1] = nm1;
            float rs0 = 0.0f, rs1 = 0.0f;
#pragma unroll
            for (int j = 0; j < 8; j++) {
                s[mi][j][0] = ftf32(__expf(s[mi][j][0] - nm0));
                s[mi][j][1] = ftf32(__expf(s[mi][j][1] - nm0));
                s[mi][j][2] = ftf32(__expf(s[mi][j][2] - nm1));
                s[mi][j][3] = ftf32(__expf(s[mi][j][3] - nm1));
                rs0 += s[mi][j][0] + s[mi][j][1];
                rs1 += s[mi][j][2] + s[mi][j][3];
            }
#pragma unroll
            for (int off = 1; off < 4; off <<= 1) {
                rs0 += __shfl_xor_sync(0xffffffffu, rs0, off);
                rs1 += __shfl_xor_sync(0xffffffffu, rs1, off);
            }
            lrow[mi * 2 + 0] = lrow[mi * 2 + 0] * a0 + rs0;
            lrow[mi * 2 + 1] = lrow[mi * 2 + 1] * a1 + rs1;
#pragma unroll
            for (int j = 0; j < 8; j++) {
                o[mi][j][0] *= a0; o[mi][j][1] *= a0;
                o[mi][j][2] *= a1; o[mi][j][3] *= a1;
            }
        }

        const int src0 = (lane & ~3) | (qc >> 1);
        const int src1 = src0 + 2;
        const bool odd = (qc & 1);
#pragma unroll
        for (int kc = 0; kc < 8; kc++) {
            uint32_t af[2][4];
#pragma unroll
            for (int mi = 0; mi < 2; mi++) {
                float p0 = s[mi][kc][0], p1 = s[mi][kc][1];
                float p2 = s[mi][kc][2], p3 = s[mi][kc][3];
                float t00 = __shfl_sync(0xffffffffu, p0, src0);
                float t01 = __shfl_sync(0xffffffffu, p1, src0);
                float t10 = __shfl_sync(0xffffffffu, p0, src1);
                float t11 = __shfl_sync(0xffffffffu, p1, src1);
                float u00 = __shfl_sync(0xffffffffu, p2, src0);
                float u01 = __shfl_sync(0xffffffffu, p3, src0);
                float u10 = __shfl_sync(0xffffffffu, p2, src1);
                float u11 = __shfl_sync(0xffffffffu, p3, src1);
                af[mi][0] = __float_as_uint(odd ? t01 : t00);
                af[mi][1] = __float_as_uint(odd ? u01 : u00);
                af[mi][2] = __float_as_uint(odd ? t11 : t10);
                af[mi][3] = __float_as_uint(odd ? u11 : u10);
            }
#pragma unroll
            for (int j = 0; j < 8; j++) {
                uint32_t bf[2];
                bf[0] = __float_as_uint(Vs[(kc * 8 + qc) * VSTR + j * 8 + qr]);
                bf[1] = __float_as_uint(Vs[(kc * 8 + qc + 4) * VSTR + j * 8 + qr]);
                mma_tf32(o[0][j], af[0], bf);
                mma_tf32(o[1][j], af[1], bf);
            }
        }

        __syncthreads();
        if (kt + 2 <= ktmax) { issue_tile(kt + 2, buf); cp_commit(); }
    }

    // finalize: divide by l, tf32-round (proj GEMM consumes directly)
#pragma unroll
    for (int mi = 0; mi < 2; mi++) {
        float inv0 = 1.0f / lrow[mi * 2 + 0];
        float inv1 = 1.0f / lrow[mi * 2 + 1];
        size_t out0 = (size_t)(b * NT + q0 + rw + mi * 16 + qr) * NC + h * 64;
        size_t out1 = (size_t)(b * NT + q0 + rw + mi * 16 + qr + 8) * NC + h * 64;
#pragma unroll
        for (int j = 0; j < 8; j++) {
            int c0 = j * 8 + 2 * qc;
            float2 v0; v0.x = ftf32(o[mi][j][0] * inv0); v0.y = ftf32(o[mi][j][1] * inv0);
            float2 v1; v1.x = ftf32(o[mi][j][2] * inv1); v1.y = ftf32(o[mi][j][3] * inv1);
            *(float2*)&g_y[out0 + c0] = v0;
            *(float2*)&g_y[out1 + c0] = v1;
        }
    }
}

// ---------------------------------------------------------------------------
extern "C" void kernel_launch(void* const* d_in, const int* in_sizes, int n_in,
                              void* d_out, int out_size) {
    const float* x       = (const float*)d_in[0];
    const float* W_attn  = (const float*)d_in[1];
    const float* W_proj  = (const float*)d_in[2];
    const int*   indices = (const int*)d_in[3];
    float* out = (float*)d_out;

    static float *p_y = nullptr, *p_xr = nullptr, *p_war = nullptr, *p_wpr = nullptr;
    const int attn_smem = SMEM_WORDS * 4;   // 107008 B
    if (p_y == nullptr) {
        cudaFuncSetAttribute(attn_kernel, cudaFuncAttributeMaxDynamicSharedMemorySize,
                             attn_smem);
        cudaFuncSetAttribute(gemm_tf32<NQKV, true>,
                             cudaFuncAttributeMaxDynamicSharedMemorySize, GEMM_SMEM);
        cudaFuncSetAttribute(gemm_tf32<NC, false>,
                             cudaFuncAttributeMaxDynamicSharedMemorySize, GEMM_SMEM);
        void* p;
        cudaGetSymbolAddress(&p, g_y);   p_y   = (float*)p;
        cudaGetSymbolAddress(&p, g_xr);  p_xr  = (float*)p;
        cudaGetSymbolAddress(&p, g_war); p_war = (float*)p;
        cudaGetSymbolAddress(&p, g_wpr); p_wpr = (float*)p;
    }

    // pre-round all three inputs to tf32 in one launch
    round3_kernel<<<592, 256>>>(
        (const float4*)x, (float4*)p_xr, NM * NC / 4,
        (const float4*)W_attn, (float4*)p_war, NC * NQKV / 4,
        (const float4*)W_proj, (float4*)p_wpr, NC * NC / 4);

    // QKV GEMM with fused RoPE epilogue
    gemm_tf32<NQKV, true><<<dim3(NQKV / 128, NM / 128), 256, GEMM_SMEM>>>(
        p_xr, p_war, nullptr, indices);

    attn_kernel<<<dim3(NT / 128, NH, NB), 128, attn_smem>>>(indices);

    gemm_tf32<NC, false><<<dim3(NC / 128, NM / 128), 256, GEMM_SMEM>>>(
        p_y, p_wpr, out, nullptr);
}